// round 2
// baseline (speedup 1.0000x reference)
#include <cuda_runtime.h>
#include <math.h>

#define T_TOK 16384
#define DMODEL 1280
#define NHEAD 16
#define HDIM 80
#define IDIM 5120
#define NSEG 16
#define LSEG 1024

// ---------------- scratch (static device globals; no allocation) -------------
__device__ float g_X  [(size_t)T_TOK * DMODEL];      // ln1 out
__device__ float g_QKV[(size_t)T_TOK * 3 * DMODEL];  // qkv (rope applied in-place)
__device__ float g_ATT[(size_t)T_TOK * DMODEL];      // attention out
__device__ float g_H  [(size_t)T_TOK * DMODEL];      // residual 1
__device__ float g_Y  [(size_t)T_TOK * DMODEL];      // ln2 out
__device__ float g_G  [(size_t)T_TOK * IDIM];        // silu(fc1) out

// ---------------- LayerNorm ---------------------------------------------------
__global__ __launch_bounds__(256) void ln_kernel(
    const float* __restrict__ x, const float* __restrict__ w,
    const float* __restrict__ b, float* __restrict__ y)
{
    int row = blockIdx.x;
    const float* xr = x + (size_t)row * DMODEL;
    float v[5];
    float s = 0.f, s2 = 0.f;
#pragma unroll
    for (int j = 0; j < 5; ++j) {
        v[j] = xr[threadIdx.x + j * 256];
        s += v[j];
        s2 += v[j] * v[j];
    }
#pragma unroll
    for (int o = 16; o; o >>= 1) {
        s  += __shfl_xor_sync(0xffffffffu, s,  o);
        s2 += __shfl_xor_sync(0xffffffffu, s2, o);
    }
    __shared__ float sh[16];
    int wid = threadIdx.x >> 5, lane = threadIdx.x & 31;
    if (!lane) { sh[wid] = s; sh[wid + 8] = s2; }
    __syncthreads();
    if (threadIdx.x == 0) {
        float S = 0.f, S2 = 0.f;
#pragma unroll
        for (int i = 0; i < 8; ++i) { S += sh[i]; S2 += sh[i + 8]; }
        sh[0] = S; sh[8] = S2;
    }
    __syncthreads();
    float mean = sh[0] * (1.f / DMODEL);
    float var  = sh[8] * (1.f / DMODEL) - mean * mean;
    float inv  = rsqrtf(var + 1e-6f);
    float* yr = y + (size_t)row * DMODEL;
#pragma unroll
    for (int j = 0; j < 5; ++j) {
        int c = threadIdx.x + j * 256;
        yr[c] = (v[j] - mean) * inv * w[c] + b[c];
    }
}

// ---------------- RoPE (in place on q,k halves of QKV) ------------------------
__global__ __launch_bounds__(256) void rope_kernel(
    float* __restrict__ QKV, const float* __restrict__ cosp,
    const float* __restrict__ sinp)
{
    int idx = blockIdx.x * blockDim.x + threadIdx.x;  // over T*H*40 pairs
    if (idx >= T_TOK * NHEAD * 40) return;
    int d = idx % 40;
    int h = (idx / 40) % NHEAD;
    int t = idx / (40 * NHEAD);
    float c1 = cosp[t * HDIM + d],      s1 = sinp[t * HDIM + d];
    float c2 = cosp[t * HDIM + d + 40], s2 = sinp[t * HDIM + d + 40];
    size_t base = (size_t)t * (3 * DMODEL) + h * HDIM;
    // q
    float q1 = QKV[base + d], q2 = QKV[base + d + 40];
    QKV[base + d]      = q1 * c1 - q2 * s1;
    QKV[base + d + 40] = q2 * c2 + q1 * s2;
    // k
    base += DMODEL;
    float k1 = QKV[base + d], k2 = QKV[base + d + 40];
    QKV[base + d]      = k1 * c1 - k2 * s1;
    QKV[base + d + 40] = k2 * c2 + k1 * s2;
}

// ---------------- Flash attention (per seg/head/32-query tile) ----------------
__global__ __launch_bounds__(128) void attn_kernel(
    const float* __restrict__ QKV, float* __restrict__ O)
{
    __shared__ float Qs[32][81];
    __shared__ float KVs[64][81];
    __shared__ float S[32][68];

    int tid = threadIdx.x;
    int r = tid >> 2, cg = tid & 3;
    int qt = blockIdx.x, head = blockIdx.y, seg = blockIdx.z;
    int q0 = seg * LSEG + qt * 32;
    const float scale = 0.11180339887498948f;  // 1/sqrt(80)

    for (int i = tid; i < 32 * 20; i += 128) {
        int row = i / 20, c4 = (i % 20) * 4;
        float4 v = *(const float4*)(QKV + (size_t)(q0 + row) * (3 * DMODEL) + head * HDIM + c4);
        Qs[row][c4 + 0] = v.x * scale;
        Qs[row][c4 + 1] = v.y * scale;
        Qs[row][c4 + 2] = v.z * scale;
        Qs[row][c4 + 3] = v.w * scale;
    }

    float acc[20];
#pragma unroll
    for (int j = 0; j < 20; ++j) acc[j] = 0.f;
    float m = -1e30f, l = 0.f;

    for (int kt = 0; kt < LSEG / 64; ++kt) {
        int k0 = seg * LSEG + kt * 64;
        __syncthreads();  // prev PV done (and Qs visible on first iter)
        // load K tile
        for (int i = tid; i < 64 * 20; i += 128) {
            int row = i / 20, c4 = (i % 20) * 4;
            float4 v = *(const float4*)(QKV + (size_t)(k0 + row) * (3 * DMODEL) + DMODEL + head * HDIM + c4);
            KVs[row][c4 + 0] = v.x; KVs[row][c4 + 1] = v.y;
            KVs[row][c4 + 2] = v.z; KVs[row][c4 + 3] = v.w;
        }
        __syncthreads();

        float dot[16];
#pragma unroll
        for (int i = 0; i < 16; ++i) dot[i] = 0.f;
#pragma unroll 8
        for (int kk = 0; kk < HDIM; ++kk) {
            float q = Qs[r][kk];
#pragma unroll
            for (int i = 0; i < 16; ++i) dot[i] += q * KVs[cg + 4 * i][kk];
        }

        float smax = dot[0];
#pragma unroll
        for (int i = 1; i < 16; ++i) smax = fmaxf(smax, dot[i]);
        smax = fmaxf(smax, __shfl_xor_sync(0xffffffffu, smax, 1));
        smax = fmaxf(smax, __shfl_xor_sync(0xffffffffu, smax, 2));
        float newm = fmaxf(m, smax);
        float corr = __expf(m - newm);
        float psum = 0.f;
#pragma unroll
        for (int i = 0; i < 16; ++i) {
            float p = __expf(dot[i] - newm);
            S[r][cg + 4 * i] = p;
            psum += p;
        }
        psum += __shfl_xor_sync(0xffffffffu, psum, 1);
        psum += __shfl_xor_sync(0xffffffffu, psum, 2);
        l = l * corr + psum;
        m = newm;
#pragma unroll
        for (int j = 0; j < 20; ++j) acc[j] *= corr;

        __syncthreads();  // S written, K reads done -> reuse KVs for V
        for (int i = tid; i < 64 * 20; i += 128) {
            int row = i / 20, c4 = (i % 20) * 4;
            float4 v = *(const float4*)(QKV + (size_t)(k0 + row) * (3 * DMODEL) + 2 * DMODEL + head * HDIM + c4);
            KVs[row][c4 + 0] = v.x; KVs[row][c4 + 1] = v.y;
            KVs[row][c4 + 2] = v.z; KVs[row][c4 + 3] = v.w;
        }
        __syncthreads();

#pragma unroll 4
        for (int kk = 0; kk < 64; ++kk) {
            float p = S[r][kk];
#pragma unroll
            for (int j = 0; j < 20; ++j) acc[j] += p * KVs[kk][cg * 20 + j];
        }
    }

    float inv = 1.f / l;
    size_t ob = (size_t)(q0 + r) * DMODEL + head * HDIM + cg * 20;
#pragma unroll
    for (int j = 0; j < 20; ++j) O[ob + j] = acc[j] * inv;
}

// ---------------- Tiled SGEMM: C[M,N] = A[M,K] @ B[N,K]^T (+epilogue) ---------
// epi: 0 = +bias, 1 = +bias + residual, 2 = silu(+bias)
__global__ __launch_bounds__(256) void gemm_kernel(
    const float* __restrict__ A, const float* __restrict__ B,
    const float* __restrict__ bias, const float* __restrict__ res,
    float* __restrict__ C, int M, int N, int K, int epi)
{
    __shared__ float As[16][132];
    __shared__ float Bs[16][132];

    int tid = threadIdx.x;
    int lr = tid >> 2;          // 0..63
    int lk = (tid & 3) << 2;    // 0,4,8,12
    const float* Ap = A + (size_t)(blockIdx.y * 128 + lr) * K + lk;
    const float* Bp = B + (size_t)(blockIdx.x * 128 + lr) * K + lk;
    int tx = tid & 15, ty = tid >> 4;

    float acc[8][8];
#pragma unroll
    for (int i = 0; i < 8; ++i)
#pragma unroll
        for (int j = 0; j < 8; ++j) acc[i][j] = 0.f;

    for (int k0 = 0; k0 < K; k0 += 16) {
        float4 a0 = *(const float4*)Ap;
        float4 a1 = *(const float4*)(Ap + (size_t)64 * K);
        float4 b0 = *(const float4*)Bp;
        float4 b1 = *(const float4*)(Bp + (size_t)64 * K);
        __syncthreads();
        As[lk + 0][lr] = a0.x; As[lk + 1][lr] = a0.y;
        As[lk + 2][lr] = a0.z; As[lk + 3][lr] = a0.w;
        As[lk + 0][lr + 64] = a1.x; As[lk + 1][lr + 64] = a1.y;
        As[lk + 2][lr + 64] = a1.z; As[lk + 3][lr + 64] = a1.w;
        Bs[lk + 0][lr] = b0.x; Bs[lk + 1][lr] = b0.y;
        Bs[lk + 2][lr] = b0.z; Bs[lk + 3][lr] = b0.w;
        Bs[lk + 0][lr + 64] = b1.x; Bs[lk + 1][lr + 64] = b1.y;
        Bs[lk + 2][lr + 64] = b1.z; Bs[lk + 3][lr + 64] = b1.w;
        __syncthreads();

#pragma unroll
        for (int kk = 0; kk < 16; ++kk) {
            float4 af0 = *(const float4*)&As[kk][ty * 8];
            float4 af1 = *(const float4*)&As[kk][ty * 8 + 4];
            float4 bf0 = *(const float4*)&Bs[kk][tx * 8];
            float4 bf1 = *(const float4*)&Bs[kk][tx * 8 + 4];
            float ar[8] = {af0.x, af0.y, af0.z, af0.w, af1.x, af1.y, af1.z, af1.w};
            float br[8] = {bf0.x, bf0.y, bf0.z, bf0.w, bf1.x, bf1.y, bf1.z, bf1.w};
#pragma unroll
            for (int i = 0; i < 8; ++i)
#pragma unroll
                for (int j = 0; j < 8; ++j) acc[i][j] += ar[i] * br[j];
        }
        Ap += 16;
        Bp += 16;
    }

    int crow = blockIdx.y * 128 + ty * 8;
    int ccol = blockIdx.x * 128 + tx * 8;
    float bv[8];
#pragma unroll
    for (int j = 0; j < 8; ++j) bv[j] = bias[ccol + j];

#pragma unroll
    for (int i = 0; i < 8; ++i) {
        float* Crow = C + (size_t)(crow + i) * N + ccol;
        const float* Rrow = (epi == 1) ? (res + (size_t)(crow + i) * N + ccol) : nullptr;
#pragma unroll
        for (int j = 0; j < 8; ++j) {
            float v = acc[i][j] + bv[j];
            if (epi == 1) v += Rrow[j];
            else if (epi == 2) v = v * (1.f / (1.f + __expf(-v)));
            Crow[j] = v;
        }
    }
}

// ---------------- launch ------------------------------------------------------
extern "C" void kernel_launch(void* const* d_in, const int* in_sizes, int n_in,
                              void* d_out, int out_size)
{
    const float* hidden = (const float*)d_in[0];
    const float* cosp   = (const float*)d_in[1];
    const float* sinp   = (const float*)d_in[2];
    const float* ln1w   = (const float*)d_in[3];
    const float* ln1b   = (const float*)d_in[4];
    const float* ln2w   = (const float*)d_in[5];
    const float* ln2b   = (const float*)d_in[6];
    const float* qkvw   = (const float*)d_in[7];
    const float* qkvb   = (const float*)d_in[8];
    const float* projw  = (const float*)d_in[9];
    const float* projb  = (const float*)d_in[10];
    const float* fc1w   = (const float*)d_in[11];
    const float* fc1b   = (const float*)d_in[12];
    const float* fc2w   = (const float*)d_in[13];
    const float* fc2b   = (const float*)d_in[14];
    float* out = (float*)d_out;

    void *pX, *pQKV, *pATT, *pH, *pY, *pG;
    cudaGetSymbolAddress(&pX, g_X);
    cudaGetSymbolAddress(&pQKV, g_QKV);
    cudaGetSymbolAddress(&pATT, g_ATT);
    cudaGetSymbolAddress(&pH, g_H);
    cudaGetSymbolAddress(&pY, g_Y);
    cudaGetSymbolAddress(&pG, g_G);
    float* X = (float*)pX;
    float* QKV = (float*)pQKV;
    float* ATT = (float*)pATT;
    float* Hb = (float*)pH;
    float* Y = (float*)pY;
    float* G = (float*)pG;

    // 1. ln1
    ln_kernel<<<T_TOK, 256>>>(hidden, ln1w, ln1b, X);
    // 2. qkv = X @ qkv_w^T + qkv_b
    gemm_kernel<<<dim3(3 * DMODEL / 128, T_TOK / 128), 256>>>(
        X, qkvw, qkvb, nullptr, QKV, T_TOK, 3 * DMODEL, DMODEL, 0);
    // 3. rope on q,k
    rope_kernel<<<(T_TOK * NHEAD * 40 + 255) / 256, 256>>>(QKV, cosp, sinp);
    // 4. attention
    attn_kernel<<<dim3(LSEG / 32, NHEAD, NSEG), 128>>>(QKV, ATT);
    // 5. h = hidden + ATT @ proj_w^T + proj_b
    gemm_kernel<<<dim3(DMODEL / 128, T_TOK / 128), 256>>>(
        ATT, projw, projb, hidden, Hb, T_TOK, DMODEL, DMODEL, 1);
    // 6. ln2
    ln_kernel<<<T_TOK, 256>>>(Hb, ln2w, ln2b, Y);
    // 7. G = silu(Y @ fc1_w^T + fc1_b)
    gemm_kernel<<<dim3(IDIM / 128, T_TOK / 128), 256>>>(
        Y, fc1w, fc1b, nullptr, G, T_TOK, IDIM, DMODEL, 2);
    // 8. out = h + G @ fc2_w^T + fc2_b
    gemm_kernel<<<dim3(DMODEL / 128, T_TOK / 128), 256>>>(
        G, fc2w, fc2b, Hb, out, T_TOK, DMODEL, IDIM, 1);
}

// round 3
// speedup vs baseline: 1.8586x; 1.8586x over previous
#include <cuda_runtime.h>
#include <math.h>
#include <stdint.h>

#define T_TOK 16384
#define DMODEL 1280
#define NHEAD 16
#define HDIM 80
#define IDIM 5120
#define NSEG 16
#define LSEG 1024

// ---------------- scratch (static device globals; no allocation) -------------
__device__ float g_X  [(size_t)T_TOK * DMODEL];      // ln1 out
__device__ float g_QKV[(size_t)T_TOK * 3 * DMODEL];  // qkv (rope applied in-place)
__device__ float g_ATT[(size_t)T_TOK * DMODEL];      // attention out
__device__ float g_H  [(size_t)T_TOK * DMODEL];      // residual 1
__device__ float g_Y  [(size_t)T_TOK * DMODEL];      // ln2 out
__device__ float g_G  [(size_t)T_TOK * IDIM];        // silu(fc1) out

// ---------------- LayerNorm ---------------------------------------------------
__global__ __launch_bounds__(256) void ln_kernel(
    const float* __restrict__ x, const float* __restrict__ w,
    const float* __restrict__ b, float* __restrict__ y)
{
    int row = blockIdx.x;
    const float* xr = x + (size_t)row * DMODEL;
    float v[5];
    float s = 0.f, s2 = 0.f;
#pragma unroll
    for (int j = 0; j < 5; ++j) {
        v[j] = xr[threadIdx.x + j * 256];
        s += v[j];
        s2 += v[j] * v[j];
    }
#pragma unroll
    for (int o = 16; o; o >>= 1) {
        s  += __shfl_xor_sync(0xffffffffu, s,  o);
        s2 += __shfl_xor_sync(0xffffffffu, s2, o);
    }
    __shared__ float sh[16];
    int wid = threadIdx.x >> 5, lane = threadIdx.x & 31;
    if (!lane) { sh[wid] = s; sh[wid + 8] = s2; }
    __syncthreads();
    if (threadIdx.x == 0) {
        float S = 0.f, S2 = 0.f;
#pragma unroll
        for (int i = 0; i < 8; ++i) { S += sh[i]; S2 += sh[i + 8]; }
        sh[0] = S; sh[8] = S2;
    }
    __syncthreads();
    float mean = sh[0] * (1.f / DMODEL);
    float var  = sh[8] * (1.f / DMODEL) - mean * mean;
    float inv  = rsqrtf(var + 1e-6f);
    float* yr = y + (size_t)row * DMODEL;
#pragma unroll
    for (int j = 0; j < 5; ++j) {
        int c = threadIdx.x + j * 256;
        yr[c] = (v[j] - mean) * inv * w[c] + b[c];
    }
}

// ---------------- RoPE (in place on q,k halves of QKV) ------------------------
__global__ __launch_bounds__(256) void rope_kernel(
    float* __restrict__ QKV, const float* __restrict__ cosp,
    const float* __restrict__ sinp)
{
    int idx = blockIdx.x * blockDim.x + threadIdx.x;  // over T*H*40 pairs
    if (idx >= T_TOK * NHEAD * 40) return;
    int d = idx % 40;
    int h = (idx / 40) % NHEAD;
    int t = idx / (40 * NHEAD);
    float c1 = cosp[t * HDIM + d],      s1 = sinp[t * HDIM + d];
    float c2 = cosp[t * HDIM + d + 40], s2 = sinp[t * HDIM + d + 40];
    size_t base = (size_t)t * (3 * DMODEL) + h * HDIM;
    // q
    float q1 = QKV[base + d], q2 = QKV[base + d + 40];
    QKV[base + d]      = q1 * c1 - q2 * s1;
    QKV[base + d + 40] = q2 * c2 + q1 * s2;
    // k
    base += DMODEL;
    float k1 = QKV[base + d], k2 = QKV[base + d + 40];
    QKV[base + d]      = k1 * c1 - k2 * s1;
    QKV[base + d + 40] = k2 * c2 + k1 * s2;
}

// ---------------- Flash attention (per seg/head/32-query tile) ----------------
__global__ __launch_bounds__(128) void attn_kernel(
    const float* __restrict__ QKV, float* __restrict__ O)
{
    __shared__ float Qs[32][81];
    __shared__ float KVs[64][81];
    __shared__ float S[32][68];

    int tid = threadIdx.x;
    int r = tid >> 2, cg = tid & 3;
    int qt = blockIdx.x, head = blockIdx.y, seg = blockIdx.z;
    int q0 = seg * LSEG + qt * 32;
    const float scale = 0.11180339887498948f;  // 1/sqrt(80)

    for (int i = tid; i < 32 * 20; i += 128) {
        int row = i / 20, c4 = (i % 20) * 4;
        float4 v = *(const float4*)(QKV + (size_t)(q0 + row) * (3 * DMODEL) + head * HDIM + c4);
        Qs[row][c4 + 0] = v.x * scale;
        Qs[row][c4 + 1] = v.y * scale;
        Qs[row][c4 + 2] = v.z * scale;
        Qs[row][c4 + 3] = v.w * scale;
    }

    float acc[20];
#pragma unroll
    for (int j = 0; j < 20; ++j) acc[j] = 0.f;
    float m = -1e30f, l = 0.f;

    for (int kt = 0; kt < LSEG / 64; ++kt) {
        int k0 = seg * LSEG + kt * 64;
        __syncthreads();  // prev PV done (and Qs visible on first iter)
        // load K tile
        for (int i = tid; i < 64 * 20; i += 128) {
            int row = i / 20, c4 = (i % 20) * 4;
            float4 v = *(const float4*)(QKV + (size_t)(k0 + row) * (3 * DMODEL) + DMODEL + head * HDIM + c4);
            KVs[row][c4 + 0] = v.x; KVs[row][c4 + 1] = v.y;
            KVs[row][c4 + 2] = v.z; KVs[row][c4 + 3] = v.w;
        }
        __syncthreads();

        float dot[16];
#pragma unroll
        for (int i = 0; i < 16; ++i) dot[i] = 0.f;
#pragma unroll 8
        for (int kk = 0; kk < HDIM; ++kk) {
            float q = Qs[r][kk];
#pragma unroll
            for (int i = 0; i < 16; ++i) dot[i] += q * KVs[cg + 4 * i][kk];
        }

        float smax = dot[0];
#pragma unroll
        for (int i = 1; i < 16; ++i) smax = fmaxf(smax, dot[i]);
        smax = fmaxf(smax, __shfl_xor_sync(0xffffffffu, smax, 1));
        smax = fmaxf(smax, __shfl_xor_sync(0xffffffffu, smax, 2));
        float newm = fmaxf(m, smax);
        float corr = __expf(m - newm);
        float psum = 0.f;
#pragma unroll
        for (int i = 0; i < 16; ++i) {
            float p = __expf(dot[i] - newm);
            S[r][cg + 4 * i] = p;
            psum += p;
        }
        psum += __shfl_xor_sync(0xffffffffu, psum, 1);
        psum += __shfl_xor_sync(0xffffffffu, psum, 2);
        l = l * corr + psum;
        m = newm;
#pragma unroll
        for (int j = 0; j < 20; ++j) acc[j] *= corr;

        __syncthreads();  // S written, K reads done -> reuse KVs for V
        for (int i = tid; i < 64 * 20; i += 128) {
            int row = i / 20, c4 = (i % 20) * 4;
            float4 v = *(const float4*)(QKV + (size_t)(k0 + row) * (3 * DMODEL) + 2 * DMODEL + head * HDIM + c4);
            KVs[row][c4 + 0] = v.x; KVs[row][c4 + 1] = v.y;
            KVs[row][c4 + 2] = v.z; KVs[row][c4 + 3] = v.w;
        }
        __syncthreads();

#pragma unroll 4
        for (int kk = 0; kk < 64; ++kk) {
            float p = S[r][kk];
#pragma unroll
            for (int j = 0; j < 20; ++j) acc[j] += p * KVs[kk][cg * 20 + j];
        }
    }

    float inv = 1.f / l;
    size_t ob = (size_t)(q0 + r) * DMODEL + head * HDIM + cg * 20;
#pragma unroll
    for (int j = 0; j < 20; ++j) O[ob + j] = acc[j] * inv;
}

// ---------------- TF32 tensor-core GEMM: C[M,N] = A[M,K] @ B[N,K]^T -----------
// epi: 0 = +bias, 1 = +bias + residual, 2 = silu(+bias)
__device__ __forceinline__ uint32_t f2tf32(float x) {
    uint32_t r;
    asm("cvt.rna.tf32.f32 %0, %1;" : "=r"(r) : "f"(x));
    return r;
}

__device__ __forceinline__ void mma_tf32(float* c, const uint32_t* a, const uint32_t* b) {
    asm volatile(
        "mma.sync.aligned.m16n8k8.row.col.f32.tf32.tf32.f32 "
        "{%0,%1,%2,%3}, {%4,%5,%6,%7}, {%8,%9}, {%0,%1,%2,%3};"
        : "+f"(c[0]), "+f"(c[1]), "+f"(c[2]), "+f"(c[3])
        : "r"(a[0]), "r"(a[1]), "r"(a[2]), "r"(a[3]), "r"(b[0]), "r"(b[1]));
}

__global__ __launch_bounds__(256) void gemm_tf32_kernel(
    const float* __restrict__ A, const float* __restrict__ B,
    const float* __restrict__ bias, const float* __restrict__ res,
    float* __restrict__ C, int M, int N, int K, int epi)
{
    // row-major smem, stride 36 words -> fragment LDS banks (4g + t) all distinct
    __shared__ uint32_t As[128][36];
    __shared__ uint32_t Bs[128][36];

    int tid = threadIdx.x;
    int wid = tid >> 5, lane = tid & 31;
    int g = lane >> 2, t = lane & 3;
    int warpM = wid >> 2;   // 0..1 -> 64-row slab
    int warpN = wid & 3;    // 0..3 -> 32-col slab
    int mrow0 = warpM * 64;
    int ncol0 = warpN * 32;

    const float* Ag = A + (size_t)(blockIdx.y * 128) * K;
    const float* Bg = B + (size_t)(blockIdx.x * 128) * K;

    float acc[4][4][4];
#pragma unroll
    for (int mt = 0; mt < 4; ++mt)
#pragma unroll
        for (int nt = 0; nt < 4; ++nt)
#pragma unroll
            for (int q = 0; q < 4; ++q) acc[mt][nt][q] = 0.f;

    for (int k0 = 0; k0 < K; k0 += 32) {
        __syncthreads();   // previous chunk's LDS complete
#pragma unroll
        for (int i = 0; i < 4; ++i) {
            int idx = tid + i * 256;
            int row = idx >> 3, kq = (idx & 7) << 2;
            float4 av = *(const float4*)(Ag + (size_t)row * K + k0 + kq);
            float4 bv = *(const float4*)(Bg + (size_t)row * K + k0 + kq);
            uint32_t* ap = &As[row][kq];
            ap[0] = f2tf32(av.x); ap[1] = f2tf32(av.y);
            ap[2] = f2tf32(av.z); ap[3] = f2tf32(av.w);
            uint32_t* bp = &Bs[row][kq];
            bp[0] = f2tf32(bv.x); bp[1] = f2tf32(bv.y);
            bp[2] = f2tf32(bv.z); bp[3] = f2tf32(bv.w);
        }
        __syncthreads();

#pragma unroll
        for (int ks = 0; ks < 4; ++ks) {
            int kb = ks * 8 + t;
            uint32_t af[4][4], bf[4][2];
#pragma unroll
            for (int mt = 0; mt < 4; ++mt) {
                int r = mrow0 + mt * 16 + g;
                af[mt][0] = As[r][kb];
                af[mt][1] = As[r + 8][kb];
                af[mt][2] = As[r][kb + 4];
                af[mt][3] = As[r + 8][kb + 4];
            }
#pragma unroll
            for (int nt = 0; nt < 4; ++nt) {
                int c = ncol0 + nt * 8 + g;
                bf[nt][0] = Bs[c][kb];
                bf[nt][1] = Bs[c][kb + 4];
            }
#pragma unroll
            for (int mt = 0; mt < 4; ++mt)
#pragma unroll
                for (int nt = 0; nt < 4; ++nt)
                    mma_tf32(acc[mt][nt], af[mt], bf[nt]);
        }
    }

    // epilogue: c0:(g,2t) c1:(g,2t+1) c2:(g+8,2t) c3:(g+8,2t+1)
#pragma unroll
    for (int mt = 0; mt < 4; ++mt) {
#pragma unroll
        for (int nt = 0; nt < 4; ++nt) {
            int row = blockIdx.y * 128 + mrow0 + mt * 16 + g;
            int col = blockIdx.x * 128 + ncol0 + nt * 8 + 2 * t;
            float b0 = bias[col], b1 = bias[col + 1];
#pragma unroll
            for (int half = 0; half < 2; ++half) {
                int r = row + half * 8;
                float v0 = acc[mt][nt][half * 2 + 0] + b0;
                float v1 = acc[mt][nt][half * 2 + 1] + b1;
                if (epi == 1) {
                    const float* rp = res + (size_t)r * N + col;
                    v0 += rp[0];
                    v1 += rp[1];
                } else if (epi == 2) {
                    v0 = v0 * (1.f / (1.f + __expf(-v0)));
                    v1 = v1 * (1.f / (1.f + __expf(-v1)));
                }
                *(float2*)(C + (size_t)r * N + col) = make_float2(v0, v1);
            }
        }
    }
}

// ---------------- launch ------------------------------------------------------
extern "C" void kernel_launch(void* const* d_in, const int* in_sizes, int n_in,
                              void* d_out, int out_size)
{
    const float* hidden = (const float*)d_in[0];
    const float* cosp   = (const float*)d_in[1];
    const float* sinp   = (const float*)d_in[2];
    const float* ln1w   = (const float*)d_in[3];
    const float* ln1b   = (const float*)d_in[4];
    const float* ln2w   = (const float*)d_in[5];
    const float* ln2b   = (const float*)d_in[6];
    const float* qkvw   = (const float*)d_in[7];
    const float* qkvb   = (const float*)d_in[8];
    const float* projw  = (const float*)d_in[9];
    const float* projb  = (const float*)d_in[10];
    const float* fc1w   = (const float*)d_in[11];
    const float* fc1b   = (const float*)d_in[12];
    const float* fc2w   = (const float*)d_in[13];
    const float* fc2b   = (const float*)d_in[14];
    float* out = (float*)d_out;

    void *pX, *pQKV, *pATT, *pH, *pY, *pG;
    cudaGetSymbolAddress(&pX, g_X);
    cudaGetSymbolAddress(&pQKV, g_QKV);
    cudaGetSymbolAddress(&pATT, g_ATT);
    cudaGetSymbolAddress(&pH, g_H);
    cudaGetSymbolAddress(&pY, g_Y);
    cudaGetSymbolAddress(&pG, g_G);
    float* X = (float*)pX;
    float* QKV = (float*)pQKV;
    float* ATT = (float*)pATT;
    float* Hb = (float*)pH;
    float* Y = (float*)pY;
    float* G = (float*)pG;

    // 1. ln1
    ln_kernel<<<T_TOK, 256>>>(hidden, ln1w, ln1b, X);
    // 2. qkv = X @ qkv_w^T + qkv_b
    gemm_tf32_kernel<<<dim3(3 * DMODEL / 128, T_TOK / 128), 256>>>(
        X, qkvw, qkvb, nullptr, QKV, T_TOK, 3 * DMODEL, DMODEL, 0);
    // 3. rope on q,k
    rope_kernel<<<(T_TOK * NHEAD * 40 + 255) / 256, 256>>>(QKV, cosp, sinp);
    // 4. attention
    attn_kernel<<<dim3(LSEG / 32, NHEAD, NSEG), 128>>>(QKV, ATT);
    // 5. h = hidden + ATT @ proj_w^T + proj_b
    gemm_tf32_kernel<<<dim3(DMODEL / 128, T_TOK / 128), 256>>>(
        ATT, projw, projb, hidden, Hb, T_TOK, DMODEL, DMODEL, 1);
    // 6. ln2
    ln_kernel<<<T_TOK, 256>>>(Hb, ln2w, ln2b, Y);
    // 7. G = silu(Y @ fc1_w^T + fc1_b)
    gemm_tf32_kernel<<<dim3(IDIM / 128, T_TOK / 128), 256>>>(
        Y, fc1w, fc1b, nullptr, G, T_TOK, IDIM, DMODEL, 2);
    // 8. out = h + G @ fc2_w^T + fc2_b
    gemm_tf32_kernel<<<dim3(DMODEL / 128, T_TOK / 128), 256>>>(
        G, fc2w, fc2b, Hb, out, T_TOK, DMODEL, IDIM, 1);
}

// round 4
// speedup vs baseline: 2.0470x; 1.1014x over previous
#include <cuda_runtime.h>
#include <math.h>
#include <stdint.h>

#define T_TOK 16384
#define DMODEL 1280
#define NHEAD 16
#define HDIM 80
#define IDIM 5120
#define NSEG 16
#define LSEG 1024

// ---------------- scratch (static device globals; no allocation) -------------
__device__ float g_X  [(size_t)T_TOK * DMODEL];      // ln1 out (tf32-rounded)
__device__ float g_QKV[(size_t)T_TOK * 3 * DMODEL];  // qkv (rope applied in-place)
__device__ float g_ATT[(size_t)T_TOK * DMODEL];      // attention out (tf32-rounded)
__device__ float g_H  [(size_t)T_TOK * DMODEL];      // residual 1
__device__ float g_Y  [(size_t)T_TOK * DMODEL];      // ln2 out (tf32-rounded)
__device__ float g_G  [(size_t)T_TOK * IDIM];        // silu(fc1) out (tf32-rounded)
// tf32-rounded weights
__device__ float g_Wq [(size_t)3 * DMODEL * DMODEL];
__device__ float g_Wp [(size_t)DMODEL * DMODEL];
__device__ float g_W1 [(size_t)IDIM * DMODEL];
__device__ float g_W2 [(size_t)DMODEL * IDIM];

__device__ __forceinline__ uint32_t f2tf32(float x) {
    uint32_t r;
    asm("cvt.rna.tf32.f32 %0, %1;" : "=r"(r) : "f"(x));
    return r;
}
__device__ __forceinline__ float tf32r(float x) { return __uint_as_float(f2tf32(x)); }

// ---------------- weight pre-round -------------------------------------------
__global__ __launch_bounds__(256) void round_tf32_kernel(
    const float* __restrict__ src, float* __restrict__ dst, int n4)
{
    int i = blockIdx.x * blockDim.x + threadIdx.x;
    if (i >= n4) return;
    float4 v = ((const float4*)src)[i];
    v.x = tf32r(v.x); v.y = tf32r(v.y); v.z = tf32r(v.z); v.w = tf32r(v.w);
    ((float4*)dst)[i] = v;
}

// ---------------- LayerNorm (emits tf32-rounded) ------------------------------
__global__ __launch_bounds__(256) void ln_kernel(
    const float* __restrict__ x, const float* __restrict__ w,
    const float* __restrict__ b, float* __restrict__ y)
{
    int row = blockIdx.x;
    const float* xr = x + (size_t)row * DMODEL;
    float v[5];
    float s = 0.f, s2 = 0.f;
#pragma unroll
    for (int j = 0; j < 5; ++j) {
        v[j] = xr[threadIdx.x + j * 256];
        s += v[j];
        s2 += v[j] * v[j];
    }
#pragma unroll
    for (int o = 16; o; o >>= 1) {
        s  += __shfl_xor_sync(0xffffffffu, s,  o);
        s2 += __shfl_xor_sync(0xffffffffu, s2, o);
    }
    __shared__ float sh[16];
    int wid = threadIdx.x >> 5, lane = threadIdx.x & 31;
    if (!lane) { sh[wid] = s; sh[wid + 8] = s2; }
    __syncthreads();
    if (threadIdx.x == 0) {
        float S = 0.f, S2 = 0.f;
#pragma unroll
        for (int i = 0; i < 8; ++i) { S += sh[i]; S2 += sh[i + 8]; }
        sh[0] = S; sh[8] = S2;
    }
    __syncthreads();
    float mean = sh[0] * (1.f / DMODEL);
    float var  = sh[8] * (1.f / DMODEL) - mean * mean;
    float inv  = rsqrtf(var + 1e-6f);
    float* yr = y + (size_t)row * DMODEL;
#pragma unroll
    for (int j = 0; j < 5; ++j) {
        int c = threadIdx.x + j * 256;
        yr[c] = tf32r((v[j] - mean) * inv * w[c] + b[c]);
    }
}

// ---------------- RoPE (in place on q,k halves of QKV) ------------------------
__global__ __launch_bounds__(256) void rope_kernel(
    float* __restrict__ QKV, const float* __restrict__ cosp,
    const float* __restrict__ sinp)
{
    int idx = blockIdx.x * blockDim.x + threadIdx.x;  // over T*H*40 pairs
    if (idx >= T_TOK * NHEAD * 40) return;
    int d = idx % 40;
    int h = (idx / 40) % NHEAD;
    int t = idx / (40 * NHEAD);
    float c1 = cosp[t * HDIM + d],      s1 = sinp[t * HDIM + d];
    float c2 = cosp[t * HDIM + d + 40], s2 = sinp[t * HDIM + d + 40];
    size_t base = (size_t)t * (3 * DMODEL) + h * HDIM;
    float q1 = QKV[base + d], q2 = QKV[base + d + 40];
    QKV[base + d]      = q1 * c1 - q2 * s1;
    QKV[base + d + 40] = q2 * c2 + q1 * s2;
    base += DMODEL;
    float k1 = QKV[base + d], k2 = QKV[base + d + 40];
    QKV[base + d]      = k1 * c1 - k2 * s1;
    QKV[base + d + 40] = k2 * c2 + k1 * s2;
}

// ---------------- Flash attention (per seg/head/32-query tile) ----------------
__global__ __launch_bounds__(128) void attn_kernel(
    const float* __restrict__ QKV, float* __restrict__ O)
{
    __shared__ float Qs[32][81];
    __shared__ float KVs[64][81];
    __shared__ float S[32][68];

    int tid = threadIdx.x;
    int r = tid >> 2, cg = tid & 3;
    int qt = blockIdx.x, head = blockIdx.y, seg = blockIdx.z;
    int q0 = seg * LSEG + qt * 32;
    const float scale = 0.11180339887498948f;

    for (int i = tid; i < 32 * 20; i += 128) {
        int row = i / 20, c4 = (i % 20) * 4;
        float4 v = *(const float4*)(QKV + (size_t)(q0 + row) * (3 * DMODEL) + head * HDIM + c4);
        Qs[row][c4 + 0] = v.x * scale;
        Qs[row][c4 + 1] = v.y * scale;
        Qs[row][c4 + 2] = v.z * scale;
        Qs[row][c4 + 3] = v.w * scale;
    }

    float acc[20];
#pragma unroll
    for (int j = 0; j < 20; ++j) acc[j] = 0.f;
    float m = -1e30f, l = 0.f;

    for (int kt = 0; kt < LSEG / 64; ++kt) {
        int k0 = seg * LSEG + kt * 64;
        __syncthreads();
        for (int i = tid; i < 64 * 20; i += 128) {
            int row = i / 20, c4 = (i % 20) * 4;
            float4 v = *(const float4*)(QKV + (size_t)(k0 + row) * (3 * DMODEL) + DMODEL + head * HDIM + c4);
            KVs[row][c4 + 0] = v.x; KVs[row][c4 + 1] = v.y;
            KVs[row][c4 + 2] = v.z; KVs[row][c4 + 3] = v.w;
        }
        __syncthreads();

        float dot[16];
#pragma unroll
        for (int i = 0; i < 16; ++i) dot[i] = 0.f;
#pragma unroll 8
        for (int kk = 0; kk < HDIM; ++kk) {
            float q = Qs[r][kk];
#pragma unroll
            for (int i = 0; i < 16; ++i) dot[i] += q * KVs[cg + 4 * i][kk];
        }

        float smax = dot[0];
#pragma unroll
        for (int i = 1; i < 16; ++i) smax = fmaxf(smax, dot[i]);
        smax = fmaxf(smax, __shfl_xor_sync(0xffffffffu, smax, 1));
        smax = fmaxf(smax, __shfl_xor_sync(0xffffffffu, smax, 2));
        float newm = fmaxf(m, smax);
        float corr = __expf(m - newm);
        float psum = 0.f;
#pragma unroll
        for (int i = 0; i < 16; ++i) {
            float p = __expf(dot[i] - newm);
            S[r][cg + 4 * i] = p;
            psum += p;
        }
        psum += __shfl_xor_sync(0xffffffffu, psum, 1);
        psum += __shfl_xor_sync(0xffffffffu, psum, 2);
        l = l * corr + psum;
        m = newm;
#pragma unroll
        for (int j = 0; j < 20; ++j) acc[j] *= corr;

        __syncthreads();
        for (int i = tid; i < 64 * 20; i += 128) {
            int row = i / 20, c4 = (i % 20) * 4;
            float4 v = *(const float4*)(QKV + (size_t)(k0 + row) * (3 * DMODEL) + 2 * DMODEL + head * HDIM + c4);
            KVs[row][c4 + 0] = v.x; KVs[row][c4 + 1] = v.y;
            KVs[row][c4 + 2] = v.z; KVs[row][c4 + 3] = v.w;
        }
        __syncthreads();

#pragma unroll 4
        for (int kk = 0; kk < 64; ++kk) {
            float p = S[r][kk];
#pragma unroll
            for (int j = 0; j < 20; ++j) acc[j] += p * KVs[kk][cg * 20 + j];
        }
    }

    float inv = 1.f / l;
    size_t ob = (size_t)(q0 + r) * DMODEL + head * HDIM + cg * 20;
#pragma unroll
    for (int j = 0; j < 20; ++j) O[ob + j] = tf32r(acc[j] * inv);
}

// ---------------- TF32 pipelined GEMM: C[M,N] = A[M,K] @ B[N,K]^T -------------
// Inputs A,B must already be tf32-rounded (mma truncation is then exact).
// epi: 0 = +bias, 1 = +bias + residual, 2 = silu(+bias), tf32-rounded output
__device__ __forceinline__ void mma_tf32(float* c, const uint32_t* a, const uint32_t* b) {
    asm volatile(
        "mma.sync.aligned.m16n8k8.row.col.f32.tf32.tf32.f32 "
        "{%0,%1,%2,%3}, {%4,%5,%6,%7}, {%8,%9}, {%0,%1,%2,%3};"
        : "+f"(c[0]), "+f"(c[1]), "+f"(c[2]), "+f"(c[3])
        : "r"(a[0]), "r"(a[1]), "r"(a[2]), "r"(a[3]), "r"(b[0]), "r"(b[1]));
}
__device__ __forceinline__ void cp_async16(uint32_t saddr, const void* gptr) {
    asm volatile("cp.async.cg.shared.global [%0], [%1], 16;" :: "r"(saddr), "l"(gptr));
}

#define PITCH 36
#define STAGE_WORDS (2 * 128 * PITCH)   // A + B tile per stage
#define GEMM_SMEM (2 * STAGE_WORDS * 4) // 73728 bytes

__global__ __launch_bounds__(256) void gemm_tf32_pipe(
    const float* __restrict__ A, const float* __restrict__ B,
    const float* __restrict__ bias, const float* __restrict__ res,
    float* __restrict__ C, int M, int N, int K, int epi)
{
    extern __shared__ uint32_t smem[];
    uint32_t smem_base = (uint32_t)__cvta_generic_to_shared(smem);

    int tid = threadIdx.x;
    int wid = tid >> 5, lane = tid & 31;
    int g = lane >> 2, t = lane & 3;
    int mrow0 = (wid >> 2) * 64;
    int ncol0 = (wid & 3) * 32;

    const float* Ag = A + (size_t)(blockIdx.y * 128) * K;
    const float* Bg = B + (size_t)(blockIdx.x * 128) * K;

    int ldrow = tid >> 3;            // 0..31
    int ldkq  = (tid & 7) << 2;      // 0,4,..28

    float acc[4][4][4];
#pragma unroll
    for (int mt = 0; mt < 4; ++mt)
#pragma unroll
        for (int nt = 0; nt < 4; ++nt)
#pragma unroll
            for (int q = 0; q < 4; ++q) acc[mt][nt][q] = 0.f;

    const int NC = K >> 5;

    // issue stage loads for chunk c into stage s
    auto issue = [&](int c, int s) {
        int k0 = c << 5;
        uint32_t sa = smem_base + (uint32_t)s * (STAGE_WORDS * 4);
        uint32_t sb = sa + 128 * PITCH * 4;
#pragma unroll
        for (int i = 0; i < 4; ++i) {
            int row = ldrow + i * 32;
            uint32_t off = ((uint32_t)row * PITCH + ldkq) * 4;
            cp_async16(sa + off, Ag + (size_t)row * K + k0 + ldkq);
            cp_async16(sb + off, Bg + (size_t)row * K + k0 + ldkq);
        }
        asm volatile("cp.async.commit_group;");
    };

    issue(0, 0);

    for (int c = 0; c < NC; ++c) {
        if (c + 1 < NC) {
            issue(c + 1, (c + 1) & 1);
            asm volatile("cp.async.wait_group 1;");
        } else {
            asm volatile("cp.async.wait_group 0;");
        }
        __syncthreads();

        const uint32_t* Asp = smem + (size_t)(c & 1) * STAGE_WORDS;
        const uint32_t* Bsp = Asp + 128 * PITCH;
#pragma unroll
        for (int ks = 0; ks < 4; ++ks) {
            int kb = ks * 8 + t;
            uint32_t af[4][4], bf[4][2];
#pragma unroll
            for (int mt = 0; mt < 4; ++mt) {
                int r = mrow0 + mt * 16 + g;
                af[mt][0] = Asp[r * PITCH + kb];
                af[mt][1] = Asp[(r + 8) * PITCH + kb];
                af[mt][2] = Asp[r * PITCH + kb + 4];
                af[mt][3] = Asp[(r + 8) * PITCH + kb + 4];
            }
#pragma unroll
            for (int nt = 0; nt < 4; ++nt) {
                int cc = ncol0 + nt * 8 + g;
                bf[nt][0] = Bsp[cc * PITCH + kb];
                bf[nt][1] = Bsp[cc * PITCH + kb + 4];
            }
#pragma unroll
            for (int mt = 0; mt < 4; ++mt)
#pragma unroll
                for (int nt = 0; nt < 4; ++nt)
                    mma_tf32(acc[mt][nt], af[mt], bf[nt]);
        }
        __syncthreads();
    }

    // epilogue: c0:(g,2t) c1:(g,2t+1) c2:(g+8,2t) c3:(g+8,2t+1)
#pragma unroll
    for (int mt = 0; mt < 4; ++mt) {
#pragma unroll
        for (int nt = 0; nt < 4; ++nt) {
            int row = blockIdx.y * 128 + mrow0 + mt * 16 + g;
            int col = blockIdx.x * 128 + ncol0 + nt * 8 + 2 * t;
            float b0 = bias[col], b1 = bias[col + 1];
#pragma unroll
            for (int half = 0; half < 2; ++half) {
                int r = row + half * 8;
                float v0 = acc[mt][nt][half * 2 + 0] + b0;
                float v1 = acc[mt][nt][half * 2 + 1] + b1;
                if (epi == 1) {
                    const float* rp = res + (size_t)r * N + col;
                    v0 += rp[0];
                    v1 += rp[1];
                } else if (epi == 2) {
                    v0 = tf32r(v0 * (1.f / (1.f + __expf(-v0))));
                    v1 = tf32r(v1 * (1.f / (1.f + __expf(-v1))));
                }
                *(float2*)(C + (size_t)r * N + col) = make_float2(v0, v1);
            }
        }
    }
}

// ---------------- launch ------------------------------------------------------
extern "C" void kernel_launch(void* const* d_in, const int* in_sizes, int n_in,
                              void* d_out, int out_size)
{
    const float* hidden = (const float*)d_in[0];
    const float* cosp   = (const float*)d_in[1];
    const float* sinp   = (const float*)d_in[2];
    const float* ln1w   = (const float*)d_in[3];
    const float* ln1b   = (const float*)d_in[4];
    const float* ln2w   = (const float*)d_in[5];
    const float* ln2b   = (const float*)d_in[6];
    const float* qkvw   = (const float*)d_in[7];
    const float* qkvb   = (const float*)d_in[8];
    const float* projw  = (const float*)d_in[9];
    const float* projb  = (const float*)d_in[10];
    const float* fc1w   = (const float*)d_in[11];
    const float* fc1b   = (const float*)d_in[12];
    const float* fc2w   = (const float*)d_in[13];
    const float* fc2b   = (const float*)d_in[14];
    float* out = (float*)d_out;

    void *pX, *pQKV, *pATT, *pH, *pY, *pG, *pWq, *pWp, *pW1, *pW2;
    cudaGetSymbolAddress(&pX, g_X);
    cudaGetSymbolAddress(&pQKV, g_QKV);
    cudaGetSymbolAddress(&pATT, g_ATT);
    cudaGetSymbolAddress(&pH, g_H);
    cudaGetSymbolAddress(&pY, g_Y);
    cudaGetSymbolAddress(&pG, g_G);
    cudaGetSymbolAddress(&pWq, g_Wq);
    cudaGetSymbolAddress(&pWp, g_Wp);
    cudaGetSymbolAddress(&pW1, g_W1);
    cudaGetSymbolAddress(&pW2, g_W2);
    float* X = (float*)pX;
    float* QKV = (float*)pQKV;
    float* ATT = (float*)pATT;
    float* Hb = (float*)pH;
    float* Y = (float*)pY;
    float* G = (float*)pG;
    float* Wq = (float*)pWq;
    float* Wp = (float*)pWp;
    float* W1 = (float*)pW1;
    float* W2 = (float*)pW2;

    static bool attr_set = false;
    if (!attr_set) {
        cudaFuncSetAttribute(gemm_tf32_pipe,
                             cudaFuncAttributeMaxDynamicSharedMemorySize, GEMM_SMEM);
        attr_set = true;
    }

    // 0. pre-round weights to tf32
    {
        int n4;
        n4 = 3 * DMODEL * DMODEL / 4;
        round_tf32_kernel<<<(n4 + 255) / 256, 256>>>(qkvw, Wq, n4);
        n4 = DMODEL * DMODEL / 4;
        round_tf32_kernel<<<(n4 + 255) / 256, 256>>>(projw, Wp, n4);
        n4 = IDIM * DMODEL / 4;
        round_tf32_kernel<<<(n4 + 255) / 256, 256>>>(fc1w, W1, n4);
        round_tf32_kernel<<<(n4 + 255) / 256, 256>>>(fc2w, W2, n4);
    }

    // 1. ln1 (tf32-rounded out)
    ln_kernel<<<T_TOK, 256>>>(hidden, ln1w, ln1b, X);
    // 2. qkv = X @ qkv_w^T + qkv_b
    gemm_tf32_pipe<<<dim3(3 * DMODEL / 128, T_TOK / 128), 256, GEMM_SMEM>>>(
        X, Wq, qkvb, nullptr, QKV, T_TOK, 3 * DMODEL, DMODEL, 0);
    // 3. rope on q,k
    rope_kernel<<<(T_TOK * NHEAD * 40 + 255) / 256, 256>>>(QKV, cosp, sinp);
    // 4. attention (tf32-rounded out)
    attn_kernel<<<dim3(LSEG / 32, NHEAD, NSEG), 128>>>(QKV, ATT);
    // 5. h = hidden + ATT @ proj_w^T + proj_b
    gemm_tf32_pipe<<<dim3(DMODEL / 128, T_TOK / 128), 256, GEMM_SMEM>>>(
        ATT, Wp, projb, hidden, Hb, T_TOK, DMODEL, DMODEL, 1);
    // 6. ln2 (tf32-rounded out)
    ln_kernel<<<T_TOK, 256>>>(Hb, ln2w, ln2b, Y);
    // 7. G = silu(Y @ fc1_w^T + fc1_b)  (tf32-rounded out)
    gemm_tf32_pipe<<<dim3(IDIM / 128, T_TOK / 128), 256, GEMM_SMEM>>>(
        Y, W1, fc1b, nullptr, G, T_TOK, IDIM, DMODEL, 2);
    // 8. out = h + G @ fc2_w^T + fc2_b
    gemm_tf32_pipe<<<dim3(DMODEL / 128, T_TOK / 128), 256, GEMM_SMEM>>>(
        G, W2, fc2b, Hb, out, T_TOK, DMODEL, IDIM, 1);
}